// round 2
// baseline (speedup 1.0000x reference)
#include <cuda_runtime.h>
#include <math.h>

// Problem constants
#define Bv 64
#define Nv 17
#define Tv 512
#define Cv 64
#define Hh 4
#define DKv 16
#define PLANE (Tv*Cv)              // 32768
#define TOTAL ((size_t)Bv*Nv*Tv*Cv)

// Scratch: g (GAT output, [B,N,T,C]) and permuted residual (same layout as output)
__device__ float g_gbuf[Bv*Nv*Tv*Cv];
__device__ float g_resbuf[Bv*Nv*Tv*Cv];

// ---------------------------------------------------------------------------
// K1: GAT. One block = 128 threads = two 64-thread groups, each handling one
// (b, t). Per group: load x[b,:,t,:] (17x64) to smem, matmul vs W (smem),
// attention (s/t decomposition, masked softmax over j, sum over i), write
// g = h*scale + h0 and the permuted residual.
// ---------------------------------------------------------------------------
__global__ __launch_bounds__(128) void gat_kernel(
    const float* __restrict__ x, const int* __restrict__ adj,
    const float* __restrict__ W, const float* __restrict__ a)
{
    __shared__ __align__(16) float sW[64*68];   // W row-major, stride 68 (272B rows: 16B multiple)
    __shared__ __align__(16) float sH0[2][17*68];
    __shared__ float sBias[17*17];
    __shared__ float sa[32];
    __shared__ float sH [2][17*68];
    __shared__ float sS[2][68], sT[2][68], sM[2][68], sDinv[2][68], sScale[2][68];

    const int tid = threadIdx.x;
    const int b   = blockIdx.y;
    const int grp = tid >> 6;
    const int o   = tid & 63;
    const int t   = blockIdx.x * 2 + grp;

    // Cooperative block-wide loads
    for (int i = tid; i < 64*64; i += 128) sW[(i>>6)*68 + (i&63)] = W[i];
    for (int i = tid; i < 289; i += 128)   sBias[i] = adj[b*289 + i] ? 0.0f : -1e9f;
    if (tid < 32) sa[tid] = a[tid];

    // h0 tile: sH0[n*68 + c] = x[b,n,t,c]
    const float* xb = x + ((size_t)b*Nv*Tv + t) * Cv;
    #pragma unroll
    for (int n = 0; n < 17; n++) sH0[grp][n*68 + o] = xb[(size_t)n*PLANE + o];
    __syncthreads();

    // Matmul: h[n,o] = sum_c h0[n,c] * W[o,c]
    float acc[17];
    #pragma unroll
    for (int n = 0; n < 17; n++) acc[n] = 0.0f;
    #pragma unroll 4
    for (int c = 0; c < 64; c += 4) {
        const float4 w4 = *(const float4*)&sW[o*68 + c];
        #pragma unroll
        for (int n = 0; n < 17; n++) {
            const float4 x4 = *(const float4*)&sH0[grp][n*68 + c];
            acc[n] += w4.x*x4.x + w4.y*x4.y + w4.z*x4.z + w4.w*x4.w;
        }
    }
    #pragma unroll
    for (int n = 0; n < 17; n++) sH[grp][n*68 + o] = acc[n];

    // Permuted residual: res[b,n,t,c] = x[b,(64n+c)%17, t, (64n+c)/17]
    {
        float* resb = g_resbuf + ((size_t)b*Nv*Tv + t) * Cv;
        #pragma unroll
        for (int n = 0; n < 17; n++) {
            const int q = n*64 + o;
            resb[(size_t)n*PLANE + o] = sH0[grp][(q % 17)*68 + (q / 17)];
        }
    }
    __syncthreads();

    // s[n,h] = h[n, 16h+d] . a[0:16], t[n,h] = . a[16:32]   (68 tasks on 64 threads)
    for (int k = o; k < 68; k += 64) {
        const int n = k >> 2, hh = k & 3;
        float ss = 0.0f, tt = 0.0f;
        #pragma unroll
        for (int d = 0; d < 16; d++) {
            const float hv = sH[grp][n*68 + hh*16 + d];
            ss += hv * sa[d];
            tt += hv * sa[16 + d];
        }
        sS[grp][k] = ss; sT[grp][k] = tt;
    }
    __syncthreads();

    // Per (i,h): row max and 1/denominator of softmax over j
    for (int k = o; k < 68; k += 64) {
        const int i = k >> 2, hh = k & 3;
        const float si = sS[grp][k];
        float m = -3.4e38f;
        #pragma unroll
        for (int j = 0; j < 17; j++) {
            float z = si + sT[grp][j*4 + hh];
            z = (z > 0.0f) ? z : 0.2f * z;
            z += sBias[i*17 + j];
            m = fmaxf(m, z);
        }
        float sum = 0.0f;
        #pragma unroll
        for (int j = 0; j < 17; j++) {
            float z = si + sT[grp][j*4 + hh];
            z = (z > 0.0f) ? z : 0.2f * z;
            z += sBias[i*17 + j];
            sum += __expf(z - m);
        }
        sM[grp][k] = m; sDinv[grp][k] = 1.0f / sum;
    }
    __syncthreads();

    // scale[j,h] = sum_i alpha[i,j,h]
    for (int k = o; k < 68; k += 64) {
        const int j = k >> 2, hh = k & 3;
        const float tj = sT[grp][j*4 + hh];
        float sc = 0.0f;
        #pragma unroll
        for (int i = 0; i < 17; i++) {
            float z = sS[grp][i*4 + hh] + tj;
            z = (z > 0.0f) ? z : 0.2f * z;
            z += sBias[i*17 + j];
            sc += __expf(z - sM[grp][i*4 + hh]) * sDinv[grp][i*4 + hh];
        }
        sScale[grp][k] = sc;
    }
    __syncthreads();

    // g = h * scale + h0, stored [B,N,T,C]
    {
        float* gb = g_gbuf + ((size_t)b*Nv*Tv + t) * Cv;
        const int hh = o >> 4;
        #pragma unroll
        for (int n = 0; n < 17; n++) {
            gb[(size_t)n*PLANE + o] =
                sH[grp][n*68 + o] * sScale[grp][n*4 + hh] + sH0[grp][n*68 + o];
        }
    }
}

// ---------------------------------------------------------------------------
// K2: fused TCN (conv1+BN+GELU -> conv2+BN+GELU) + residual + output.
// Conv axis = contiguous memory of each (b,n) plane; "channel" = flat/512.
// One block handles a 64-position chunk of one plane (all 64 conv channels).
// ---------------------------------------------------------------------------
__device__ __forceinline__ float gelu_exact(float v) {
    return 0.5f * v * (1.0f + erff(v * 0.70710678118654752f));
}

__global__ __launch_bounds__(256) void tcn_kernel(
    const float* __restrict__ w1, const float* __restrict__ gamma1, const float* __restrict__ beta1,
    const float* __restrict__ w2, const float* __restrict__ gamma2, const float* __restrict__ beta2,
    float* __restrict__ out)
{
    __shared__ float vt[64*71];     // conv-1 input tile: 64 ch x (64 + 6 halo), stride 71 (odd)
    __shared__ float y1[64*69];     // conv-1 output:     64 ch x (64 + 4 halo), stride 69 (odd)
    __shared__ float s_w1a[64], s_w1b[64], s_w1c[64], s_g1[64], s_b1[64];
    __shared__ float s_w2a[64], s_w2b[64], s_w2c[64], s_g2[64], s_b2[64];

    const int tid   = threadIdx.x;
    const int plane = blockIdx.y;           // b*17 + n
    const int t0    = blockIdx.x * 64;
    const float rs  = rsqrtf(1.0f + 1e-5f);

    if (tid < 64) {
        s_w1a[tid] = w1[tid*3+0]; s_w1b[tid] = w1[tid*3+1]; s_w1c[tid] = w1[tid*3+2];
        s_g1[tid]  = gamma1[tid] * rs;      s_b1[tid] = beta1[tid];
        s_w2a[tid] = w2[tid*3+0]; s_w2b[tid] = w2[tid*3+1]; s_w2c[tid] = w2[tid*3+2];
        s_g2[tid]  = gamma2[tid] * rs;      s_b2[tid] = beta2[tid];
    }

    const float* gp = g_gbuf + (size_t)plane * PLANE;
    for (int idx = tid; idx < 64*70; idx += 256) {
        const int c = idx / 70, i = idx - c*70;
        const int t = t0 - 6 + i;
        vt[c*71 + i] = (t >= 0) ? gp[c*512 + t] : 0.0f;
    }
    __syncthreads();

    // conv1 + BN + GELU at tau = t0-4 .. t0+63 (zero for tau<0: that's layer-2's pad)
    for (int idx = tid; idx < 64*68; idx += 256) {
        const int j = idx >> 6, c = idx & 63;
        const int tau = t0 - 4 + j;
        const float v0 = vt[c*71 + j], v1 = vt[c*71 + j + 1], v2 = vt[c*71 + j + 2];
        const float val = (s_w1a[c]*v0 + s_w1b[c]*v1 + s_w1c[c]*v2) * s_g1[c] + s_b1[c];
        y1[c*69 + j] = (tau >= 0) ? gelu_exact(val) : 0.0f;
    }
    __syncthreads();

    // conv2 (dil=2) + BN + GELU + residual; output at out[plane, t, c] (lanes over c: coalesced)
    const float* rp = g_resbuf + (size_t)plane * PLANE;
    float* op = out + (size_t)plane * PLANE;
    for (int idx = tid; idx < 64*64; idx += 256) {
        const int tl = idx >> 6, c = idx & 63;
        const float a0 = y1[c*69 + tl], a1 = y1[c*69 + tl + 2], a2 = y1[c*69 + tl + 4];
        const float val = (s_w2a[c]*a0 + s_w2b[c]*a1 + s_w2c[c]*a2) * s_g2[c] + s_b2[c];
        const int oi = (t0 + tl)*64 + c;
        op[oi] = gelu_exact(val) + rp[oi];
    }
}

// ---------------------------------------------------------------------------
extern "C" void kernel_launch(void* const* d_in, const int* in_sizes, int n_in,
                              void* d_out, int out_size)
{
    (void)in_sizes; (void)n_in; (void)out_size;
    const float* x      = (const float*)d_in[0];
    const int*   adj    = (const int*)  d_in[1];
    const float* W      = (const float*)d_in[2];
    const float* a      = (const float*)d_in[3];
    const float* w1     = (const float*)d_in[4];
    const float* gamma1 = (const float*)d_in[5];
    const float* beta1  = (const float*)d_in[6];
    const float* w2     = (const float*)d_in[7];
    const float* gamma2 = (const float*)d_in[8];
    const float* beta2  = (const float*)d_in[9];
    float* out = (float*)d_out;

    gat_kernel<<<dim3(Tv/2, Bv), 128>>>(x, adj, W, a);
    tcn_kernel<<<dim3(Tv/64, Bv*Nv), 256>>>(w1, gamma1, beta1, w2, gamma2, beta2, out);
}

// round 4
// speedup vs baseline: 1.1113x; 1.1113x over previous
#include <cuda_runtime.h>
#include <math.h>

// Problem constants
#define Bv 64
#define Nv 17
#define Tv 512
#define Cv 64
#define PLANE (Tv*Cv)              // 32768

__device__ float g_gbuf[Bv*Nv*Tv*Cv];
__device__ float g_resbuf[Bv*Nv*Tv*Cv];

typedef unsigned long long u64;

__device__ __forceinline__ void ffma2(u64 &acc, u64 a, u64 b) {
    asm("fma.rn.f32x2 %0, %1, %2, %0;" : "+l"(acc) : "l"(a), "l"(b));
}
__device__ __forceinline__ float lo_f(u64 v) { return __uint_as_float((unsigned)(v & 0xffffffffu)); }
__device__ __forceinline__ float hi_f(u64 v) { return __uint_as_float((unsigned)(v >> 32)); }

// ---------------------------------------------------------------------------
// K1: GAT. Block = 256 threads = 4 groups of 64; each group one (b,t).
// Packed f32x2 matmul (c-pair packing), no-max softmax with E-cache reuse of
// the x-tile smem buffer.
// ---------------------------------------------------------------------------
__global__ __launch_bounds__(256) void gat_kernel(
    const float* __restrict__ x, const int* __restrict__ adj,
    const float* __restrict__ W, const float* __restrict__ a)
{
    __shared__ __align__(16) float sW[64*68];       // W[o][c] at o*68+c
    __shared__ __align__(16) float sX[4][17*68];    // x-tile -> h -> E-cache (reused)
    __shared__ float sMask[17*17];                  // 1.0 / 0.0
    __shared__ float sa[32];
    __shared__ float sS[4][68], sT[4][68], sScale[4][68];

    const int tid = threadIdx.x;
    const int b   = blockIdx.y;
    const int grp = tid >> 6;
    const int o   = tid & 63;
    const int t   = blockIdx.x * 4 + grp;

    for (int i = tid; i < 64*64; i += 256) sW[(i>>6)*68 + (i&63)] = W[i];
    for (int i = tid; i < 289; i += 256)   sMask[i] = adj[b*289 + i] ? 1.0f : 0.0f;
    if (tid < 32) sa[tid] = a[tid];

    // x tile: sX[grp][n*68 + c] = x[b,n,t,c]
    const float* xb = x + ((size_t)b*Nv*Tv + t) * Cv;
    #pragma unroll
    for (int n = 0; n < 17; n++) sX[grp][n*68 + o] = xb[(size_t)n*PLANE + o];
    __syncthreads();

    // ---- matmul h[n,o] = sum_c x[n,c] * W[o,c]  (f32x2 over c-pairs) ----
    u64 acc[17];
    #pragma unroll
    for (int n = 0; n < 17; n++) acc[n] = 0ull;
    #pragma unroll 4
    for (int cs = 0; cs < 64; cs += 4) {
        const ulonglong2 wv = *(const ulonglong2*)&sW[o*68 + cs];
        #pragma unroll
        for (int n = 0; n < 17; n++) {
            const ulonglong2 xv = *(const ulonglong2*)&sX[grp][n*68 + cs];
            ffma2(acc[n], xv.x, wv.x);
            ffma2(acc[n], xv.y, wv.y);
        }
    }
    float h[17], h0r[17];
    #pragma unroll
    for (int n = 0; n < 17; n++) h[n] = lo_f(acc[n]) + hi_f(acc[n]);

    // keep h0 values this lane needs for the g output
    #pragma unroll
    for (int n = 0; n < 17; n++) h0r[n] = sX[grp][n*68 + o];

    // Permuted residual: res[b,n,t,c] = x[b,(64n+c)%17, t, (64n+c)/17]
    {
        float* resb = g_resbuf + ((size_t)b*Nv*Tv + t) * Cv;
        #pragma unroll
        for (int n = 0; n < 17; n++) {
            const int q = n*64 + o;
            resb[(size_t)n*PLANE + o] = sX[grp][(q % 17)*68 + (q / 17)];
        }
    }
    __syncthreads();

    // write h into the (now free) sX buffer for the s/t phase
    #pragma unroll
    for (int n = 0; n < 17; n++) sX[grp][n*68 + o] = h[n];
    __syncthreads();

    // s[n,h] = h[n,16h+d].a[0:16], t = .a[16:32]
    for (int k = o; k < 68; k += 64) {
        const int n = k >> 2, hh = k & 3;
        float ss = 0.0f, tt = 0.0f;
        #pragma unroll
        for (int d = 0; d < 16; d += 4) {
            const float4 hv = *(const float4*)&sX[grp][n*68 + hh*16 + d];
            ss += hv.x*sa[d] + hv.y*sa[d+1] + hv.z*sa[d+2] + hv.w*sa[d+3];
            tt += hv.x*sa[16+d] + hv.y*sa[17+d] + hv.z*sa[18+d] + hv.w*sa[19+d];
        }
        sS[grp][k] = ss; sT[grp][k] = tt;
    }
    __syncthreads();

    // Pass A: per (i,h) compute masked exp row, rowsum, store e*dinv into E-cache (= sX)
    for (int k = o; k < 68; k += 64) {
        const int i = k >> 2, hh = k & 3;
        const float si = sS[grp][k];
        float e[17], rs = 0.0f;
        #pragma unroll
        for (int j = 0; j < 17; j++) {
            float z = si + sT[grp][j*4 + hh];
            z = (z > 0.0f) ? z : 0.2f * z;
            e[j] = __expf(z) * sMask[i*17 + j];
            rs += e[j];
        }
        if (rs == 0.0f) {   // all-masked row: softmax is shift-invariant -> unmasked softmax
            #pragma unroll
            for (int j = 0; j < 17; j++) {
                float z = si + sT[grp][j*4 + hh];
                z = (z > 0.0f) ? z : 0.2f * z;
                e[j] = __expf(z);
                rs += e[j];
            }
        }
        const float dinv = 1.0f / rs;
        #pragma unroll
        for (int j = 0; j < 17; j++) sX[grp][i*68 + j*4 + hh] = e[j] * dinv;
    }
    __syncthreads();

    // Pass B: scale[j,h] = sum_i alpha[i,j,h]
    for (int k = o; k < 68; k += 64) {
        const int j = k >> 2, hh = k & 3;
        float sc = 0.0f;
        #pragma unroll
        for (int i = 0; i < 17; i++) sc += sX[grp][i*68 + j*4 + hh];
        sScale[grp][k] = sc;
    }
    __syncthreads();

    // g = h*scale + h0
    {
        float* gb = g_gbuf + ((size_t)b*Nv*Tv + t) * Cv;
        const int hh = o >> 4;
        #pragma unroll
        for (int n = 0; n < 17; n++)
            gb[(size_t)n*PLANE + o] = h[n] * sScale[grp][n*4 + hh] + h0r[n];
    }
}

// ---------------------------------------------------------------------------
// K2: fused TCN. Phase 1 reads g straight from gmem (no input tile), phase 2
// float4-vectorized output. smem = y1 only -> full occupancy.
// ---------------------------------------------------------------------------
__device__ __forceinline__ float gelu_exact(float v) {
    return 0.5f * v * (1.0f + erff(v * 0.70710678118654752f));
}

__global__ __launch_bounds__(256) void tcn_kernel(
    const float* __restrict__ w1, const float* __restrict__ gamma1, const float* __restrict__ beta1,
    const float* __restrict__ w2, const float* __restrict__ gamma2, const float* __restrict__ beta2,
    float* __restrict__ out)
{
    __shared__ float y1[64*69];     // conv-1 output: 64 ch x (64 + 4 halo), stride 69
    __shared__ float s_w1a[64], s_w1b[64], s_w1c[64], s_g1[64], s_b1[64];
    __shared__ float s_w2a[64], s_w2b[64], s_w2c[64], s_g2[64], s_b2[64];

    const int tid   = threadIdx.x;
    const int plane = blockIdx.y;           // b*17 + n
    const int t0    = blockIdx.x * 64;
    const float rs  = rsqrtf(1.0f + 1e-5f);

    if (tid < 64) {
        s_w1a[tid] = w1[tid*3+0]; s_w1b[tid] = w1[tid*3+1]; s_w1c[tid] = w1[tid*3+2];
        s_g1[tid]  = gamma1[tid] * rs;      s_b1[tid] = beta1[tid];
        s_w2a[tid] = w2[tid*3+0]; s_w2b[tid] = w2[tid*3+1]; s_w2c[tid] = w2[tid*3+2];
        s_g2[tid]  = gamma2[tid] * rs;      s_b2[tid] = beta2[tid];
    }
    __syncthreads();

    // conv1 + BN + GELU at tau = t0-4 .. t0+63, inputs straight from gmem
    const float* gp = g_gbuf + (size_t)plane * PLANE;
    for (int idx = tid; idx < 64*68; idx += 256) {
        const int c = idx / 68, j = idx - c*68;
        const int tau = t0 - 4 + j;
        const float* gc = gp + c*512;
        const float v0 = (tau-2 >= 0) ? gc[tau-2] : 0.0f;
        const float v1 = (tau-1 >= 0) ? gc[tau-1] : 0.0f;
        const float v2 = (tau   >= 0) ? gc[tau]   : 0.0f;
        const float val = (s_w1a[c]*v0 + s_w1b[c]*v1 + s_w1c[c]*v2) * s_g1[c] + s_b1[c];
        y1[c*69 + j] = (tau >= 0) ? gelu_exact(val) : 0.0f;
    }
    __syncthreads();

    // conv2 (dil=2) + BN + GELU + residual, float4 output
    const float* rp = g_resbuf + (size_t)plane * PLANE;
    float* op = out + (size_t)plane * PLANE;
    for (int idx = tid; idx < 64*16; idx += 256) {
        const int tl = idx >> 4, cq = (idx & 15) * 4;
        float4 res = *(const float4*)&rp[(t0 + tl)*64 + cq];
        float4 ov;
        #pragma unroll
        for (int u = 0; u < 4; u++) {
            const int c = cq + u;
            const float a0 = y1[c*69 + tl], a1 = y1[c*69 + tl + 2], a2 = y1[c*69 + tl + 4];
            const float val = (s_w2a[c]*a0 + s_w2b[c]*a1 + s_w2c[c]*a2) * s_g2[c] + s_b2[c];
            ((float*)&ov)[u] = gelu_exact(val) + ((const float*)&res)[u];
        }
        *(float4*)&op[(t0 + tl)*64 + cq] = ov;
    }
}

// ---------------------------------------------------------------------------
extern "C" void kernel_launch(void* const* d_in, const int* in_sizes, int n_in,
                              void* d_out, int out_size)
{
    (void)in_sizes; (void)n_in; (void)out_size;
    const float* x      = (const float*)d_in[0];
    const int*   adj    = (const int*)  d_in[1];
    const float* W      = (const float*)d_in[2];
    const float* a      = (const float*)d_in[3];
    const float* w1     = (const float*)d_in[4];
    const float* gamma1 = (const float*)d_in[5];
    const float* beta1  = (const float*)d_in[6];
    const float* w2     = (const float*)d_in[7];
    const float* gamma2 = (const float*)d_in[8];
    const float* beta2  = (const float*)d_in[9];
    float* out = (float*)d_out;

    gat_kernel<<<dim3(Tv/4, Bv), 256>>>(x, adj, W, a);
    tcn_kernel<<<dim3(Tv/64, Bv*Nv), 256>>>(w1, gamma1, beta1, w2, gamma2, beta2, out);
}

// round 15
// speedup vs baseline: 1.3081x; 1.1771x over previous
#include <cuda_runtime.h>
#include <math.h>

// Problem constants
#define Bv 64
#define Nv 17
#define Tv 512
#define Cv 64
#define PLANE (Tv*Cv)              // 32768

__device__ float g_gbuf[Bv*Nv*Tv*Cv];
__device__ float g_resbuf[Bv*Nv*Tv*Cv];

typedef unsigned long long u64;

__device__ __forceinline__ void ffma2(u64 &acc, u64 a, u64 b) {
    asm("fma.rn.f32x2 %0, %1, %2, %0;" : "+l"(acc) : "l"(a), "l"(b));
}
__device__ __forceinline__ float lo_f(u64 v) { return __uint_as_float((unsigned)(v & 0xffffffffu)); }
__device__ __forceinline__ float hi_f(u64 v) { return __uint_as_float((unsigned)(v >> 32)); }
__device__ __forceinline__ void gbar(int id) {   // per-group named barrier (64 threads)
    asm volatile("bar.sync %0, 64;" :: "r"(id) : "memory");
}

// ---------------------------------------------------------------------------
// K1: GAT. Block = 256 threads = 4 groups of 64; each group one (b, t).
// Block-wide sync only for the shared W tile; groups otherwise decoupled via
// named barriers. f32x2 matmul, no-max softmax, raw-E cache + dinv-weighted
// column sums.
// ---------------------------------------------------------------------------
__global__ __launch_bounds__(256) void gat_kernel(
    const float* __restrict__ x, const int* __restrict__ adj,
    const float* __restrict__ W, const float* __restrict__ a)
{
    __shared__ __align__(16) float sW[64*68];       // W[o][c] at o*68+c
    __shared__ __align__(16) float sX[4][17*68];    // x-tile -> h -> E-cache (reused)
    __shared__ float sMask[17*17];                  // 1.0 / 0.0
    __shared__ float sa[32];
    __shared__ float sS[4][68], sT[4][68], sDinv[4][68], sScale[4][68];

    const int tid = threadIdx.x;
    const int b   = blockIdx.y;
    const int grp = tid >> 6;
    const int o   = tid & 63;
    const int t   = blockIdx.x * 4 + grp;
    const int bar = 1 + grp;

    // Cooperative block-wide loads (W via float4)
    for (int i = tid; i < 1024; i += 256) {
        const float4 w4 = *(const float4*)&W[i*4];
        *(float4*)&sW[(i>>4)*68 + (i&15)*4] = w4;
    }
    for (int i = tid; i < 289; i += 256)   sMask[i] = adj[b*289 + i] ? 1.0f : 0.0f;
    if (tid < 32) sa[tid] = a[tid];

    // x tile: sX[grp][n*68 + c] = x[b,n,t,c]
    const float* xb = x + ((size_t)b*Nv*Tv + t) * Cv;
    #pragma unroll
    for (int n = 0; n < 17; n++) sX[grp][n*68 + o] = xb[(size_t)n*PLANE + o];
    __syncthreads();

    // ---- matmul h[n,o] = sum_c x[n,c] * W[o,c]  (f32x2 over c-pairs) ----
    u64 acc[17];
    #pragma unroll
    for (int n = 0; n < 17; n++) acc[n] = 0ull;
    #pragma unroll 4
    for (int cs = 0; cs < 64; cs += 4) {
        const ulonglong2 wv = *(const ulonglong2*)&sW[o*68 + cs];
        #pragma unroll
        for (int n = 0; n < 17; n++) {
            const ulonglong2 xv = *(const ulonglong2*)&sX[grp][n*68 + cs];  // broadcast
            ffma2(acc[n], xv.x, wv.x);
            ffma2(acc[n], xv.y, wv.y);
        }
    }
    float h[17], h0r[17];
    #pragma unroll
    for (int n = 0; n < 17; n++) h[n] = lo_f(acc[n]) + hi_f(acc[n]);
    #pragma unroll
    for (int n = 0; n < 17; n++) h0r[n] = sX[grp][n*68 + o];

    // Permuted residual: res[b,n,t,c] = x[b,(64n+c)%17, t, (64n+c)/17]
    // q = n*64+o; maintain r=q%17, d=q/17 incrementally (64 = 3*17+13)
    {
        float* resb = g_resbuf + ((size_t)b*Nv*Tv + t) * Cv;
        int r = o % 17, d = o / 17;
        #pragma unroll
        for (int n = 0; n < 17; n++) {
            resb[(size_t)n*PLANE + o] = sX[grp][r*68 + d];
            r += 13; d += 3;
            if (r >= 17) { r -= 17; d += 1; }
        }
    }
    gbar(bar);                      // x-tile reads done (group-local)

    // h into (now free) sX buffer for the s/t phase
    #pragma unroll
    for (int n = 0; n < 17; n++) sX[grp][n*68 + o] = h[n];
    gbar(bar);

    // s[n,h] = h[n,16h+d].a[0:16], t = .a[16:32]
    for (int k = o; k < 68; k += 64) {
        const int n = k >> 2, hh = k & 3;
        float ss = 0.0f, tt = 0.0f;
        #pragma unroll
        for (int d = 0; d < 16; d += 4) {
            const float4 hv = *(const float4*)&sX[grp][n*68 + hh*16 + d];
            ss += hv.x*sa[d] + hv.y*sa[d+1] + hv.z*sa[d+2] + hv.w*sa[d+3];
            tt += hv.x*sa[16+d] + hv.y*sa[17+d] + hv.z*sa[18+d] + hv.w*sa[19+d];
        }
        sS[grp][k] = ss; sT[grp][k] = tt;
    }
    gbar(bar);

    // Pass A: per (i,h) masked exp row -> raw E into sX; store 1/rowsum
    for (int k = o; k < 68; k += 64) {
        const int i = k >> 2, hh = k & 3;
        const float si = sS[grp][k];
        float rs = 0.0f;
        #pragma unroll
        for (int j = 0; j < 17; j++) {
            float z = si + sT[grp][j*4 + hh];
            z = (z > 0.0f) ? z : 0.2f * z;
            const float e = __expf(z) * sMask[i*17 + j];
            sX[grp][i*68 + j*4 + hh] = e;
            rs += e;
        }
        if (rs == 0.0f) {   // all-masked row: shift-invariant -> unmasked softmax
            #pragma unroll
            for (int j = 0; j < 17; j++) {
                float z = si + sT[grp][j*4 + hh];
                z = (z > 0.0f) ? z : 0.2f * z;
                const float e = __expf(z);
                sX[grp][i*68 + j*4 + hh] = e;
                rs += e;
            }
        }
        sDinv[grp][k] = 1.0f / rs;
    }
    gbar(bar);

    // Pass B: scale[j,h] = sum_i E[i,j,h] * dinv[i,h]
    for (int k = o; k < 68; k += 64) {
        const int j = k >> 2, hh = k & 3;
        float sc = 0.0f;
        #pragma unroll
        for (int i = 0; i < 17; i++)
            sc += sX[grp][i*68 + j*4 + hh] * sDinv[grp][i*4 + hh];
        sScale[grp][k] = sc;
    }
    gbar(bar);

    // g = h*scale + h0
    {
        float* gb = g_gbuf + ((size_t)b*Nv*Tv + t) * Cv;
        const int hh = o >> 4;
        #pragma unroll
        for (int n = 0; n < 17; n++)
            gb[(size_t)n*PLANE + o] = h[n] * sScale[grp][n*4 + hh] + h0r[n];
    }
}

// ---------------------------------------------------------------------------
// K2: fused TCN. Shifts-only index mapping; boundary branch hoisted to the
// t0==0 chunk only; phase 2 float4-vectorized.
// ---------------------------------------------------------------------------
__device__ __forceinline__ float gelu_exact(float v) {
    return 0.5f * v * (1.0f + erff(v * 0.70710678118654752f));
}

__global__ __launch_bounds__(256) void tcn_kernel(
    const float* __restrict__ w1, const float* __restrict__ gamma1, const float* __restrict__ beta1,
    const float* __restrict__ w2, const float* __restrict__ gamma2, const float* __restrict__ beta2,
    float* __restrict__ out)
{
    __shared__ float y1[64*69];     // conv-1 output: 64 ch x (64 + 4 halo), stride 69
    __shared__ float s_w1a[64], s_w1b[64], s_w1c[64], s_g1[64], s_b1[64];
    __shared__ float s_w2a[64], s_w2b[64], s_w2c[64], s_g2[64], s_b2[64];

    const int tid   = threadIdx.x;
    const int plane = blockIdx.y;           // b*17 + n
    const int t0    = blockIdx.x * 64;
    const float rsc = rsqrtf(1.0f + 1e-5f);

    if (tid < 64) {
        s_w1a[tid] = w1[tid*3+0]; s_w1b[tid] = w1[tid*3+1]; s_w1c[tid] = w1[tid*3+2];
        s_g1[tid]  = gamma1[tid] * rsc;     s_b1[tid] = beta1[tid];
        s_w2a[tid] = w2[tid*3+0]; s_w2b[tid] = w2[tid*3+1]; s_w2c[tid] = w2[tid*3+2];
        s_g2[tid]  = gamma2[tid] * rsc;     s_b2[tid] = beta2[tid];
    }
    __syncthreads();

    const float* gp = g_gbuf + (size_t)plane * PLANE;
    const int w = tid >> 5, l = tid & 31;

    if (t0 != 0) {
        // predicate-free fast path: tau = t0-4+j, all loads in range
        #pragma unroll 4
        for (int k = 0; k < 16; k++) {
            const int m = w*16 + k;            // 0..127 warp-tasks
            const int c = m >> 1;
            const int j = ((m & 1) << 5) + l;  // 0..63
            const float* gc = gp + c*512 + (t0 - 6);
            const float v0 = gc[j], v1 = gc[j+1], v2 = gc[j+2];
            const float val = (s_w1a[c]*v0 + s_w1b[c]*v1 + s_w1c[c]*v2) * s_g1[c] + s_b1[c];
            y1[c*69 + j] = gelu_exact(val);
        }
        {   // tail: j = 64..67
            const int c = tid >> 2, j = 64 + (tid & 3);
            const float* gc = gp + c*512 + (t0 - 6);
            const float v0 = gc[j], v1 = gc[j+1], v2 = gc[j+2];
            const float val = (s_w1a[c]*v0 + s_w1b[c]*v1 + s_w1c[c]*v2) * s_g1[c] + s_b1[c];
            y1[c*69 + j] = gelu_exact(val);
        }
    } else {
        // boundary chunk: tau = j-4, guard loads and zero tau<0
        for (int idx = tid; idx < 64*68; idx += 256) {
            const int c = idx / 68, j = idx - c*68;
            const int tau = j - 4;
            const float* gc = gp + c*512;
            const float v0 = (tau-2 >= 0) ? gc[tau-2] : 0.0f;
            const float v1 = (tau-1 >= 0) ? gc[tau-1] : 0.0f;
            const float v2 = (tau   >= 0) ? gc[tau]   : 0.0f;
            const float val = (s_w1a[c]*v0 + s_w1b[c]*v1 + s_w1c[c]*v2) * s_g1[c] + s_b1[c];
            y1[c*69 + j] = (tau >= 0) ? gelu_exact(val) : 0.0f;
        }
    }
    __syncthreads();

    // conv2 (dil=2) + BN + GELU + residual, float4 output
    const float* rp = g_resbuf + (size_t)plane * PLANE;
    float* op = out + (size_t)plane * PLANE;
    for (int idx = tid; idx < 64*16; idx += 256) {
        const int tl = idx >> 4, cq = (idx & 15) * 4;
        const float4 res = *(const float4*)&rp[(t0 + tl)*64 + cq];
        float4 ov;
        #pragma unroll
        for (int u = 0; u < 4; u++) {
            const int c = cq + u;
            const float a0 = y1[c*69 + tl], a1 = y1[c*69 + tl + 2], a2 = y1[c*69 + tl + 4];
            const float val = (s_w2a[c]*a0 + s_w2b[c]*a1 + s_w2c[c]*a2) * s_g2[c] + s_b2[c];
            ((float*)&ov)[u] = gelu_exact(val) + ((const float*)&res)[u];
        }
        *(float4*)&op[(t0 + tl)*64 + cq] = ov;
    }
}

// ---------------------------------------------------------------------------
extern "C" void kernel_launch(void* const* d_in, const int* in_sizes, int n_in,
                              void* d_out, int out_size)
{
    (void)in_sizes; (void)n_in; (void)out_size;
    const float* x      = (const float*)d_in[0];
    const int*   adj    = (const int*)  d_in[1];
    const float* W      = (const float*)d_in[2];
    const float* a      = (const float*)d_in[3];
    const float* w1     = (const float*)d_in[4];
    const float* gamma1 = (const float*)d_in[5];
    const float* beta1  = (const float*)d_in[6];
    const float* w2     = (const float*)d_in[7];
    const float* gamma2 = (const float*)d_in[8];
    const float* beta2  = (const float*)d_in[9];
    float* out = (float*)d_out;

    gat_kernel<<<dim3(Tv/4, Bv), 256>>>(x, adj, W, a);
    tcn_kernel<<<dim3(Tv/64, Bv*Nv), 256>>>(w1, gamma1, beta1, w2, gamma2, beta2, out);
}

// round 17
// speedup vs baseline: 1.5227x; 1.1641x over previous
#include <cuda_runtime.h>
#include <math.h>

// Problem constants
#define Bv 64
#define Nv 17
#define Tv 512
#define Cv 64
#define PLANE (Tv*Cv)              // 32768
#define GRPS 4                     // warps (= groups) per gat block

__device__ float g_gbuf[Bv*Nv*Tv*Cv];
__device__ float g_resbuf[Bv*Nv*Tv*Cv];

typedef unsigned long long u64;

__device__ __forceinline__ void ffma2(u64 &acc, u64 a, u64 b) {
    asm("fma.rn.f32x2 %0, %1, %2, %0;" : "+l"(acc) : "l"(a), "l"(b));
}
__device__ __forceinline__ float lo_f(u64 v) { return __uint_as_float((unsigned)(v & 0xffffffffu)); }
__device__ __forceinline__ float hi_f(u64 v) { return __uint_as_float((unsigned)(v >> 32)); }

// ---------------------------------------------------------------------------
// K1: GAT. One WARP per (b,t); each lane computes output columns l and l+32.
// Fully warp-synchronous after the W-tile block sync. f32x2 matmul with
// 2-output amortization of the x broadcasts; no-max softmax; raw-E cache.
// ---------------------------------------------------------------------------
__global__ __launch_bounds__(128) void gat_kernel(
    const float* __restrict__ x, const int* __restrict__ adj,
    const float* __restrict__ W, const float* __restrict__ a)
{
    __shared__ __align__(16) float sW[64*68];          // W[o][c] at o*68+c
    __shared__ __align__(16) float sX[GRPS][17*68];    // x-tile -> h -> E-cache
    __shared__ float sMask[17*17];
    __shared__ float sa[32];
    __shared__ float sS[GRPS][68], sT[GRPS][68], sDinv[GRPS][68], sScale[GRPS][68];

    const int tid = threadIdx.x;
    const int b   = blockIdx.y;
    const int w   = tid >> 5;          // warp = group
    const int l   = tid & 31;
    const int t   = blockIdx.x * GRPS + w;
    const int o1  = l, o2 = l + 32;

    // Block-cooperative loads
    for (int i = tid; i < 1024; i += 128) {
        const float4 w4 = *(const float4*)&W[i*4];
        *(float4*)&sW[(i>>4)*68 + (i&15)*4] = w4;
    }
    for (int i = tid; i < 289; i += 128) sMask[i] = adj[b*289 + i] ? 1.0f : 0.0f;
    if (tid < 32) sa[tid] = a[tid];

    // x tile: sX[w][n*68 + c] = x[b,n,t,c]; lane covers c = l and l+32
    const float* xb = x + ((size_t)b*Nv*Tv + t) * Cv;
    #pragma unroll
    for (int n = 0; n < 17; n++) {
        sX[w][n*68 + o1] = xb[(size_t)n*PLANE + o1];
        sX[w][n*68 + o2] = xb[(size_t)n*PLANE + o2];
    }
    __syncthreads();

    // ---- matmul: h[n,o] = sum_c x[n,c]*W[o,c], two outputs per lane ----
    u64 acc1[17], acc2[17];
    #pragma unroll
    for (int n = 0; n < 17; n++) { acc1[n] = 0ull; acc2[n] = 0ull; }
    #pragma unroll 4
    for (int cs = 0; cs < 64; cs += 4) {
        const ulonglong2 wv1 = *(const ulonglong2*)&sW[o1*68 + cs];
        const ulonglong2 wv2 = *(const ulonglong2*)&sW[o2*68 + cs];
        #pragma unroll
        for (int n = 0; n < 17; n++) {
            const ulonglong2 xv = *(const ulonglong2*)&sX[w][n*68 + cs];  // broadcast
            ffma2(acc1[n], xv.x, wv1.x);
            ffma2(acc1[n], xv.y, wv1.y);
            ffma2(acc2[n], xv.x, wv2.x);
            ffma2(acc2[n], xv.y, wv2.y);
        }
    }
    float h1[17], h2[17], h01[17], h02[17];
    #pragma unroll
    for (int n = 0; n < 17; n++) {
        h1[n] = lo_f(acc1[n]) + hi_f(acc1[n]);
        h2[n] = lo_f(acc2[n]) + hi_f(acc2[n]);
        h01[n] = sX[w][n*68 + o1];
        h02[n] = sX[w][n*68 + o2];
    }

    // Permuted residual: res[b,n,t,c] = x[b,(64n+c)%17, t, (64n+c)/17]
    {
        float* resb = g_resbuf + ((size_t)b*Nv*Tv + t) * Cv;
        int r1 = o1 % 17, d1 = o1 / 17;
        int r2 = o2 % 17, d2 = o2 / 17;
        #pragma unroll
        for (int n = 0; n < 17; n++) {
            resb[(size_t)n*PLANE + o1] = sX[w][r1*68 + d1];
            resb[(size_t)n*PLANE + o2] = sX[w][r2*68 + d2];
            r1 += 13; d1 += 3; if (r1 >= 17) { r1 -= 17; d1 += 1; }
            r2 += 13; d2 += 3; if (r2 >= 17) { r2 -= 17; d2 += 1; }
        }
    }
    __syncwarp();                    // x-tile reads complete

    // h into sX for the cross-lane s/t phase
    #pragma unroll
    for (int n = 0; n < 17; n++) {
        sX[w][n*68 + o1] = h1[n];
        sX[w][n*68 + o2] = h2[n];
    }
    __syncwarp();

    // s[n,hh] = h[n,16hh+d].a[0:16], t = .a[16:32]   (68 tasks on 32 lanes)
    for (int k = l; k < 68; k += 32) {
        const int n = k >> 2, hh = k & 3;
        float ss = 0.0f, tt = 0.0f;
        #pragma unroll
        for (int d = 0; d < 16; d += 4) {
            const float4 hv = *(const float4*)&sX[w][n*68 + hh*16 + d];
            ss += hv.x*sa[d] + hv.y*sa[d+1] + hv.z*sa[d+2] + hv.w*sa[d+3];
            tt += hv.x*sa[16+d] + hv.y*sa[17+d] + hv.z*sa[18+d] + hv.w*sa[19+d];
        }
        sS[w][k] = ss; sT[w][k] = tt;
    }
    __syncwarp();

    // Pass A: per (i,hh) masked exp row -> raw E into sX; store 1/rowsum
    for (int k = l; k < 68; k += 32) {
        const int i = k >> 2, hh = k & 3;
        const float si = sS[w][k];
        float rs = 0.0f;
        #pragma unroll
        for (int j = 0; j < 17; j++) {
            float z = si + sT[w][j*4 + hh];
            z = (z > 0.0f) ? z : 0.2f * z;
            const float e = __expf(z) * sMask[i*17 + j];
            sX[w][i*68 + j*4 + hh] = e;
            rs += e;
        }
        if (rs == 0.0f) {   // all-masked row: shift-invariance -> unmasked softmax
            #pragma unroll
            for (int j = 0; j < 17; j++) {
                float z = si + sT[w][j*4 + hh];
                z = (z > 0.0f) ? z : 0.2f * z;
                const float e = __expf(z);
                sX[w][i*68 + j*4 + hh] = e;
                rs += e;
            }
        }
        sDinv[w][k] = 1.0f / rs;
    }
    __syncwarp();

    // Pass B: scale[j,hh] = sum_i E[i,j,hh] * dinv[i,hh]
    for (int k = l; k < 68; k += 32) {
        const int j = k >> 2, hh = k & 3;
        float sc = 0.0f;
        #pragma unroll
        for (int i = 0; i < 17; i++)
            sc += sX[w][i*68 + j*4 + hh] * sDinv[w][i*4 + hh];
        sScale[w][k] = sc;
    }
    __syncwarp();

    // g = h*scale + h0 (h, h0 in registers)
    {
        float* gb = g_gbuf + ((size_t)b*Nv*Tv + t) * Cv;
        const int hd1 = o1 >> 4, hd2 = o2 >> 4;
        #pragma unroll
        for (int n = 0; n < 17; n++) {
            gb[(size_t)n*PLANE + o1] = h1[n] * sScale[w][n*4 + hd1] + h01[n];
            gb[(size_t)n*PLANE + o2] = h2[n] * sScale[w][n*4 + hd2] + h02[n];
        }
    }
}

// ---------------------------------------------------------------------------
// K2: fused TCN (unchanged from R15: 133 us).
// ---------------------------------------------------------------------------
__device__ __forceinline__ float gelu_exact(float v) {
    return 0.5f * v * (1.0f + erff(v * 0.70710678118654752f));
}

__global__ __launch_bounds__(256) void tcn_kernel(
    const float* __restrict__ w1, const float* __restrict__ gamma1, const float* __restrict__ beta1,
    const float* __restrict__ w2, const float* __restrict__ gamma2, const float* __restrict__ beta2,
    float* __restrict__ out)
{
    __shared__ float y1[64*69];     // conv-1 output: 64 ch x (64 + 4 halo), stride 69
    __shared__ float s_w1a[64], s_w1b[64], s_w1c[64], s_g1[64], s_b1[64];
    __shared__ float s_w2a[64], s_w2b[64], s_w2c[64], s_g2[64], s_b2[64];

    const int tid   = threadIdx.x;
    const int plane = blockIdx.y;           // b*17 + n
    const int t0    = blockIdx.x * 64;
    const float rsc = rsqrtf(1.0f + 1e-5f);

    if (tid < 64) {
        s_w1a[tid] = w1[tid*3+0]; s_w1b[tid] = w1[tid*3+1]; s_w1c[tid] = w1[tid*3+2];
        s_g1[tid]  = gamma1[tid] * rsc;     s_b1[tid] = beta1[tid];
        s_w2a[tid] = w2[tid*3+0]; s_w2b[tid] = w2[tid*3+1]; s_w2c[tid] = w2[tid*3+2];
        s_g2[tid]  = gamma2[tid] * rsc;     s_b2[tid] = beta2[tid];
    }
    __syncthreads();

    const float* gp = g_gbuf + (size_t)plane * PLANE;
    const int w = tid >> 5, l = tid & 31;

    if (t0 != 0) {
        // predicate-free fast path: tau = t0-4+j, all loads in range
        #pragma unroll 4
        for (int k = 0; k < 16; k++) {
            const int m = w*16 + k;            // 0..127 warp-tasks
            const int c = m >> 1;
            const int j = ((m & 1) << 5) + l;  // 0..63
            const float* gc = gp + c*512 + (t0 - 6);
            const float v0 = gc[j], v1 = gc[j+1], v2 = gc[j+2];
            const float val = (s_w1a[c]*v0 + s_w1b[c]*v1 + s_w1c[c]*v2) * s_g1[c] + s_b1[c];
            y1[c*69 + j] = gelu_exact(val);
        }
        {   // tail: j = 64..67
            const int c = tid >> 2, j = 64 + (tid & 3);
            const float* gc = gp + c*512 + (t0 - 6);
            const float v0 = gc[j], v1 = gc[j+1], v2 = gc[j+2];
            const float val = (s_w1a[c]*v0 + s_w1b[c]*v1 + s_w1c[c]*v2) * s_g1[c] + s_b1[c];
            y1[c*69 + j] = gelu_exact(val);
        }
    } else {
        // boundary chunk: tau = j-4, guard loads and zero tau<0
        for (int idx = tid; idx < 64*68; idx += 256) {
            const int c = idx / 68, j = idx - c*68;
            const int tau = j - 4;
            const float* gc = gp + c*512;
            const float v0 = (tau-2 >= 0) ? gc[tau-2] : 0.0f;
            const float v1 = (tau-1 >= 0) ? gc[tau-1] : 0.0f;
            const float v2 = (tau   >= 0) ? gc[tau]   : 0.0f;
            const float val = (s_w1a[c]*v0 + s_w1b[c]*v1 + s_w1c[c]*v2) * s_g1[c] + s_b1[c];
            y1[c*69 + j] = (tau >= 0) ? gelu_exact(val) : 0.0f;
        }
    }
    __syncthreads();

    // conv2 (dil=2) + BN + GELU + residual, float4 output
    const float* rp = g_resbuf + (size_t)plane * PLANE;
    float* op = out + (size_t)plane * PLANE;
    for (int idx = tid; idx < 64*16; idx += 256) {
        const int tl = idx >> 4, cq = (idx & 15) * 4;
        const float4 res = *(const float4*)&rp[(t0 + tl)*64 + cq];
        float4 ov;
        #pragma unroll
        for (int u = 0; u < 4; u++) {
            const int c = cq + u;
            const float a0 = y1[c*69 + tl], a1 = y1[c*69 + tl + 2], a2 = y1[c*69 + tl + 4];
            const float val = (s_w2a[c]*a0 + s_w2b[c]*a1 + s_w2c[c]*a2) * s_g2[c] + s_b2[c];
            ((float*)&ov)[u] = gelu_exact(val) + ((const float*)&res)[u];
        }
        *(float4*)&op[(t0 + tl)*64 + cq] = ov;
    }
}

// ---------------------------------------------------------------------------
extern "C" void kernel_launch(void* const* d_in, const int* in_sizes, int n_in,
                              void* d_out, int out_size)
{
    (void)in_sizes; (void)n_in; (void)out_size;
    const float* x      = (const float*)d_in[0];
    const int*   adj    = (const int*)  d_in[1];
    const float* W      = (const float*)d_in[2];
    const float* a      = (const float*)d_in[3];
    const float* w1     = (const float*)d_in[4];
    const float* gamma1 = (const float*)d_in[5];
    const float* beta1  = (const float*)d_in[6];
    const float* w2     = (const float*)d_in[7];
    const float* gamma2 = (const float*)d_in[8];
    const float* beta2  = (const float*)d_in[9];
    float* out = (float*)d_out;

    gat_kernel<<<dim3(Tv/GRPS, Bv), 128>>>(x, adj, W, a);
    tcn_kernel<<<dim3(Tv/64, Bv*Nv), 256>>>(w1, gamma1, beta1, w2, gamma2, beta2, out);
}